// round 15
// baseline (speedup 1.0000x reference)
#include <cuda_runtime.h>
#include <cuda_fp16.h>
#include <cstdint>

#define SEQ 2048
#define CD  1024
#define NQ  3072
#define RWS 8192
#define BR  4096

// scratch (device globals; allocation forbidden)
__device__ __half g_Ah [(size_t)RWS * CD];   // fp16 concat(x,y)
__device__ __half g_Wqh[(size_t)CD * NQ];    // fp16 w_qkv [K,N]
__device__ __half g_Wph[(size_t)CD * CD];    // fp16 w_proj [K,N]
__device__ __half g_QKVh[(size_t)RWS * NQ];  // fp16 qkv [row, 3C]
__device__ __half g_Oh [(size_t)RWS * CD];   // fp16 attention out

__device__ __forceinline__ uint32_t smem_u32(const void* p) {
    uint32_t a;
    asm("{ .reg .u64 t; cvta.to.shared.u64 t, %1; cvt.u32.u64 %0, t; }" : "=r"(a) : "l"(p));
    return a;
}
__device__ __forceinline__ float ex2(float x) {
    float r; asm("ex2.approx.f32 %0, %1;" : "=f"(r) : "f"(x)); return r;
}
#define CPA16(dst, src) \
    asm volatile("cp.async.cg.shared.global [%0], [%1], 16;" :: "r"(dst), "l"(src) : "memory")
#define CP_COMMIT() asm volatile("cp.async.commit_group;" ::: "memory")
#define CP_WAIT(n)  asm volatile("cp.async.wait_group %0;" :: "n"(n) : "memory")

#define LDSM4(r0, r1, r2, r3, addr)                                         \
    asm volatile("ldmatrix.sync.aligned.m8n8.x4.shared.b16 {%0,%1,%2,%3}, [%4];" \
        : "=r"(r0), "=r"(r1), "=r"(r2), "=r"(r3) : "r"(addr))
#define LDSM4T(r0, r1, r2, r3, addr)                                        \
    asm volatile("ldmatrix.sync.aligned.m8n8.x4.trans.shared.b16 {%0,%1,%2,%3}, [%4];" \
        : "=r"(r0), "=r"(r1), "=r"(r2), "=r"(r3) : "r"(addr))

__device__ __forceinline__ void mma16816(float* d, const uint32_t* a,
                                         const uint32_t* b) {
    asm volatile(
        "mma.sync.aligned.m16n8k16.row.col.f32.f16.f16.f32 "
        "{%0,%1,%2,%3}, {%4,%5,%6,%7}, {%8,%9}, {%0,%1,%2,%3};"
        : "+f"(d[0]), "+f"(d[1]), "+f"(d[2]), "+f"(d[3])
        : "r"(a[0]), "r"(a[1]), "r"(a[2]), "r"(a[3]), "r"(b[0]), "r"(b[1]));
}
__device__ __forceinline__ uint32_t packh2(float lo, float hi) {
    __half2 h = __floats2half2_rn(lo, hi);
    return *(uint32_t*)&h;
}

// ---------------- fused conversion kernel (device globals only in device code)
__global__ __launch_bounds__(256) void conv_all(const float* __restrict__ x,
                                                const float* __restrict__ y,
                                                const float* __restrict__ w_qkv,
                                                const float* __restrict__ w_proj) {
    int blk = blockIdx.x;
    const float* src;
    __half* dst;
    size_t i;
    if (blk < 8192) {
        i = ((size_t)blk * 256 + threadIdx.x) * 4;
        src = (i < (size_t)BR * CD) ? x + i : y + (i - (size_t)BR * CD);
        dst = g_Ah + i;
    } else if (blk < 8192 + 3072) {
        i = ((size_t)(blk - 8192) * 256 + threadIdx.x) * 4;
        src = w_qkv + i;
        dst = g_Wqh + i;
    } else {
        i = ((size_t)(blk - 8192 - 3072) * 256 + threadIdx.x) * 4;
        src = w_proj + i;
        dst = g_Wph + i;
    }
    float4 v = *(const float4*)src;
    uint2 o;
    o.x = packh2(v.x, v.y); o.y = packh2(v.z, v.w);
    *(uint2*)dst = o;
}

// ---------------------------------------------------------------------------
// fp16 GEMM (R14 config): mma.m16n8k16 + ldmatrix, BK=64, 2-stage cp.async.
// 128 thr (4 warps, 64x64 warp tiles).
// smem bytes: A stage s @ s*18432 (128x72 halves), B stage s @ 36864+s*17408
// (64x136 halves). total 71680 B.
// ---------------------------------------------------------------------------
#define GEMM_SMEM_BYTES 71680
template<int SEL>
__global__ __launch_bounds__(128) void gemm_fp16(const float* __restrict__ x,
                                                 const float* __restrict__ y,
                                                 const float* __restrict__ bias,
                                                 float* __restrict__ out) {
    extern __shared__ __half sh[];
    const int N = SEL ? CD : NQ;
    const __half* __restrict__ A = SEL ? g_Oh : g_Ah;
    const __half* __restrict__ W = SEL ? g_Wph : g_Wqh;
    const int tid = threadIdx.x, wid = tid >> 5, lane = tid & 31;
    const int bm = blockIdx.y * 128, bn = blockIdx.x * 128;
    const int wr = (wid & 1) * 64, wc = (wid >> 1) * 64;
    const uint32_t sb = smem_u32(sh);

    float acc[4][8][4];
    #pragma unroll
    for (int m = 0; m < 4; m++)
        #pragma unroll
        for (int n = 0; n < 8; n++)
            #pragma unroll
            for (int r = 0; r < 4; r++) acc[m][n][r] = 0.f;

    auto issue = [&](int c) {
        int k0 = c * 64;
        uint32_t ab = (uint32_t)(c & 1) * 18432u;
        uint32_t bb = 36864u + (uint32_t)(c & 1) * 17408u;
        #pragma unroll
        for (int j = 0; j < 8; j++) {          // A: 1024 16B units
            int u = tid + j * 128;
            int row = u >> 3, c8 = (u & 7) * 8;
            CPA16(sb + ab + (uint32_t)(row * 72 + c8) * 2u,
                  A + (size_t)(bm + row) * CD + k0 + c8);
        }
        #pragma unroll
        for (int j = 0; j < 8; j++) {          // B: 1024 16B units
            int u = tid + j * 128;
            int row = u >> 4, c8 = (u & 15) * 8;
            CPA16(sb + bb + (uint32_t)(row * 136 + c8) * 2u,
                  W + (size_t)(k0 + row) * N + bn + c8);
        }
        CP_COMMIT();
    };

    issue(0);
    for (int c = 0; c < 16; c++) {
        if (c < 15) { issue(c + 1); CP_WAIT(1); }
        else        {               CP_WAIT(0); }
        __syncthreads();
        const uint32_t abase = sb + (uint32_t)(c & 1) * 18432u;
        const uint32_t bbase = sb + 36864u + (uint32_t)(c & 1) * 17408u;
        #pragma unroll
        for (int k16 = 0; k16 < 4; k16++) {
            uint32_t a[4][4];
            #pragma unroll
            for (int m = 0; m < 4; m++) {
                uint32_t addr = abase + (uint32_t)(
                    (wr + m * 16 + (lane & 15)) * 72
                    + k16 * 16 + (lane >> 4) * 8) * 2u;
                LDSM4(a[m][0], a[m][1], a[m][2], a[m][3], addr);
            }
            #pragma unroll
            for (int nt = 0; nt < 4; nt++) {
                uint32_t b[4];
                uint32_t addr = bbase + (uint32_t)(
                    (k16 * 16 + (lane & 7) + ((lane >> 3) & 1) * 8) * 136
                    + wc + nt * 16 + (lane >> 4) * 8) * 2u;
                LDSM4T(b[0], b[1], b[2], b[3], addr);
                #pragma unroll
                for (int m = 0; m < 4; m++) {
                    mma16816(acc[m][nt * 2],     a[m], &b[0]);
                    mma16816(acc[m][nt * 2 + 1], a[m], &b[2]);
                }
            }
        }
        __syncthreads();
    }

    // epilogue: direct fragment stores
    const int er = lane >> 2, ec = (lane & 3) * 2;
    #pragma unroll
    for (int m = 0; m < 4; m++) {
        int grow0 = bm + wr + m * 16 + er;
        #pragma unroll
        for (int n = 0; n < 8; n++) {
            int gcol = bn + wc + n * 8 + ec;
            if (SEL == 0) {
                *(uint32_t*)(g_QKVh + (size_t)grow0 * NQ + gcol) =
                    packh2(acc[m][n][0], acc[m][n][1]);
                *(uint32_t*)(g_QKVh + (size_t)(grow0 + 8) * NQ + gcol) =
                    packh2(acc[m][n][2], acc[m][n][3]);
            } else {
                #pragma unroll
                for (int hrow = 0; hrow < 2; hrow++) {
                    int grow = grow0 + hrow * 8;
                    const float* res = ((grow < BR) ? x + (size_t)grow * CD
                                                    : y + (size_t)(grow - BR) * CD) + gcol;
                    float2 rv = *(const float2*)res;
                    float2 bv = *(const float2*)(bias + gcol);
                    float2 o;
                    o.x = acc[m][n][hrow * 2]     + bv.x + rv.x;
                    o.y = acc[m][n][hrow * 2 + 1] + bv.y + rv.y;
                    *(float2*)(out + (size_t)grow * CD + gcol) = o;
                }
            }
        }
    }
}

// ---------------------------------------------------------------------------
// Flash attention: fp16 mma + ldmatrix + register softmax (R12 math),
// now q-tile 64 with 128 threads (4 warps x 16 q-rows) -> ~26K regs/CTA
// -> 2 CTAs/SM without spills; cross-CTA overlap hides the exp phase.
// grid (32 q-tiles of 64, 64 jobs).
// smem: Qs h[64][72] @0 (9216), KV buf b @ 9216+b*18432 (K then V h[64][72]).
// total 46080 B.
// ---------------------------------------------------------------------------
#define ATT_SMEM_BYTES 46080
__global__ __launch_bounds__(128) void attn_fa() {
    extern __shared__ __align__(16) char shc[];
    const uint32_t sb = smem_u32(shc);
    const int tid = threadIdx.x, wid = tid >> 5, lane = tid & 31;

    const int job = blockIdx.y;
    const int p = job >> 5, b = (job >> 4) & 1, h = job & 15;
    const int q0 = blockIdx.x * 64;
    const size_t base  = (size_t)(p * 2 + b) * SEQ * NQ;
    const size_t baseV = (size_t)((1 - p) * 2 + b) * SEQ * NQ;
    const __half* qp = g_QKVh + base + (size_t)h * 64;
    const __half* kp = g_QKVh + base + CD + (size_t)h * 64;
    const __half* vp = g_QKVh + baseV + 2 * CD + (size_t)h * 64;

    auto issueKV = [&](int kt) {
        uint32_t off = 9216u + (uint32_t)(kt & 1) * 18432u;
        #pragma unroll
        for (int j = 0; j < 4; j++) {
            int u = tid + j * 128;          // 0..511
            int r = u >> 3, c8 = (u & 7) * 8;
            size_t go = (size_t)(kt * 64 + r) * NQ + c8;
            uint32_t so = (uint32_t)(r * 72 + c8) * 2u;
            CPA16(sb + off + so, kp + go);
            CPA16(sb + off + 9216u + so, vp + go);
        }
        CP_COMMIT();
    };

    // stage Q (64 rows) + KV(0)
    #pragma unroll
    for (int j = 0; j < 4; j++) {
        int u = tid + j * 128;              // 0..511
        int r = u >> 3, c8 = (u & 7) * 8;
        CPA16(sb + (uint32_t)(r * 72 + c8) * 2u, qp + (size_t)(q0 + r) * NQ + c8);
    }
    issueKV(0);
    CP_WAIT(0);
    __syncthreads();

    uint32_t qa[4][4];
    #pragma unroll
    for (int c = 0; c < 4; c++) {
        uint32_t addr = sb + (uint32_t)((wid * 16 + (lane & 15)) * 72
                                        + c * 16 + (lane >> 4) * 8) * 2u;
        LDSM4(qa[c][0], qa[c][1], qa[c][2], qa[c][3], addr);
    }

    float o[8][4];
    #pragma unroll
    for (int n = 0; n < 8; n++)
        #pragma unroll
        for (int r = 0; r < 4; r++) o[n][r] = 0.f;
    float l0 = 0.f, l1 = 0.f;
    const float SC = 0.18033688f;           // D^-0.5 * log2(e)

    for (int kt = 0; kt < 32; kt++) {
        if (kt < 31) { issueKV(kt + 1); CP_WAIT(1); }
        else         {                  CP_WAIT(0); }
        __syncthreads();
        const uint32_t kbase = sb + 9216u + (uint32_t)(kt & 1) * 18432u;
        const uint32_t vbase = kbase + 9216u;

        float s[8][4];
        #pragma unroll
        for (int n = 0; n < 8; n++)
            #pragma unroll
            for (int r = 0; r < 4; r++) s[n][r] = 0.f;

        #pragma unroll
        for (int c = 0; c < 4; c++) {
            uint32_t kb[4][4];
            #pragma unroll
            for (int t = 0; t < 4; t++) {
                uint32_t addr = kbase + (uint32_t)(
                    (t * 16 + (lane & 7) + (lane >> 4) * 8) * 72
                    + c * 16 + ((lane >> 3) & 1) * 8) * 2u;
                LDSM4(kb[t][0], kb[t][1], kb[t][2], kb[t][3], addr);
            }
            #pragma unroll
            for (int t = 0; t < 4; t++) {
                mma16816(s[t * 2],     qa[c], &kb[t][0]);
                mma16816(s[t * 2 + 1], qa[c], &kb[t][2]);
            }
        }

        float rs0 = 0.f, rs1 = 0.f;
        #pragma unroll
        for (int n = 0; n < 8; n++) {
            float e0 = ex2(s[n][0] * SC), e1 = ex2(s[n][1] * SC);
            float e2 = ex2(s[n][2] * SC), e3 = ex2(s[n][3] * SC);
            s[n][0] = e0; s[n][1] = e1; s[n][2] = e2; s[n][3] = e3;
            rs0 += e0 + e1; rs1 += e2 + e3;
        }
        rs0 += __shfl_xor_sync(0xffffffffu, rs0, 1);
        rs0 += __shfl_xor_sync(0xffffffffu, rs0, 2);
        rs1 += __shfl_xor_sync(0xffffffffu, rs1, 1);
        rs1 += __shfl_xor_sync(0xffffffffu, rs1, 2);
        l0 += rs0; l1 += rs1;

        uint32_t pa[4][4];
        #pragma unroll
        for (int c2 = 0; c2 < 4; c2++) {
            pa[c2][0] = packh2(s[c2 * 2][0],     s[c2 * 2][1]);
            pa[c2][1] = packh2(s[c2 * 2][2],     s[c2 * 2][3]);
            pa[c2][2] = packh2(s[c2 * 2 + 1][0], s[c2 * 2 + 1][1]);
            pa[c2][3] = packh2(s[c2 * 2 + 1][2], s[c2 * 2 + 1][3]);
        }

        #pragma unroll
        for (int c2 = 0; c2 < 4; c2++) {
            #pragma unroll
            for (int j = 0; j < 4; j++) {
                uint32_t vb[4];
                uint32_t addr = vbase + (uint32_t)(
                    (c2 * 16 + (lane & 7) + ((lane >> 3) & 1) * 8) * 72
                    + j * 16 + (lane >> 4) * 8) * 2u;
                LDSM4T(vb[0], vb[1], vb[2], vb[3], addr);
                mma16816(o[j * 2],     pa[c2], &vb[0]);
                mma16816(o[j * 2 + 1], pa[c2], &vb[2]);
            }
        }
        __syncthreads();
    }

    // epilogue: normalize, write fp16 g_Oh
    const float inv0 = 1.f / l0, inv1 = 1.f / l1;
    const size_t rbase = (size_t)(p * 2 + b) * SEQ + q0 + wid * 16;
    const size_t r0 = rbase + (lane >> 2), r1 = r0 + 8;
    const int colb = h * 64 + (lane & 3) * 2;
    #pragma unroll
    for (int n = 0; n < 8; n++) {
        *(uint32_t*)(g_Oh + r0 * CD + colb + n * 8) =
            packh2(o[n][0] * inv0, o[n][1] * inv0);
        *(uint32_t*)(g_Oh + r1 * CD + colb + n * 8) =
            packh2(o[n][2] * inv1, o[n][3] * inv1);
    }
}

// ---------------------------------------------------------------------------
extern "C" void kernel_launch(void* const* d_in, const int* in_sizes, int n_in,
                              void* d_out, int out_size) {
    const float* x      = (const float*)d_in[0];
    const float* y      = (const float*)d_in[1];
    const float* w_qkv  = (const float*)d_in[2];
    const float* w_proj = (const float*)d_in[3];
    const float* b_proj = (const float*)d_in[4];
    float* out = (float*)d_out;

    cudaFuncSetAttribute(gemm_fp16<0>, cudaFuncAttributeMaxDynamicSharedMemorySize, GEMM_SMEM_BYTES);
    cudaFuncSetAttribute(gemm_fp16<1>, cudaFuncAttributeMaxDynamicSharedMemorySize, GEMM_SMEM_BYTES);
    cudaFuncSetAttribute(attn_fa,      cudaFuncAttributeMaxDynamicSharedMemorySize, ATT_SMEM_BYTES);

    conv_all<<<8192 + 3072 + 1024, 256>>>(x, y, w_qkv, w_proj);

    gemm_fp16<0><<<dim3(NQ / 128, RWS / 128), 128, GEMM_SMEM_BYTES>>>(x, y, nullptr, nullptr);
    attn_fa<<<dim3(SEQ / 64, 64), 128, ATT_SMEM_BYTES>>>();
    gemm_fp16<1><<<dim3(CD / 128, RWS / 128), 128, GEMM_SMEM_BYTES>>>(x, y, b_proj, out);
}

// round 16
// speedup vs baseline: 1.0337x; 1.0337x over previous
#include <cuda_runtime.h>
#include <cuda_fp16.h>
#include <cstdint>

#define SEQ 2048
#define CD  1024
#define NQ  3072
#define RWS 8192
#define BR  4096

// scratch (device globals; allocation forbidden)
__device__ __half g_Ah [(size_t)RWS * CD];   // fp16 concat(x,y)
__device__ __half g_Wqh[(size_t)CD * NQ];    // fp16 w_qkv [K,N]
__device__ __half g_Wph[(size_t)CD * CD];    // fp16 w_proj [K,N]
__device__ __half g_QKVh[(size_t)RWS * NQ];  // fp16 qkv [row, 3C]
__device__ __half g_Oh [(size_t)RWS * CD];   // fp16 attention out

__device__ __forceinline__ uint32_t smem_u32(const void* p) {
    uint32_t a;
    asm("{ .reg .u64 t; cvta.to.shared.u64 t, %1; cvt.u32.u64 %0, t; }" : "=r"(a) : "l"(p));
    return a;
}
__device__ __forceinline__ float ex2(float x) {
    float r; asm("ex2.approx.f32 %0, %1;" : "=f"(r) : "f"(x)); return r;
}
#define CPA16(dst, src) \
    asm volatile("cp.async.cg.shared.global [%0], [%1], 16;" :: "r"(dst), "l"(src) : "memory")
#define CP_COMMIT() asm volatile("cp.async.commit_group;" ::: "memory")
#define CP_WAIT(n)  asm volatile("cp.async.wait_group %0;" :: "n"(n) : "memory")

#define LDSM4(r0, r1, r2, r3, addr)                                         \
    asm volatile("ldmatrix.sync.aligned.m8n8.x4.shared.b16 {%0,%1,%2,%3}, [%4];" \
        : "=r"(r0), "=r"(r1), "=r"(r2), "=r"(r3) : "r"(addr))
#define LDSM4T(r0, r1, r2, r3, addr)                                        \
    asm volatile("ldmatrix.sync.aligned.m8n8.x4.trans.shared.b16 {%0,%1,%2,%3}, [%4];" \
        : "=r"(r0), "=r"(r1), "=r"(r2), "=r"(r3) : "r"(addr))

__device__ __forceinline__ void mma16816(float* d, const uint32_t* a,
                                         const uint32_t* b) {
    asm volatile(
        "mma.sync.aligned.m16n8k16.row.col.f32.f16.f16.f32 "
        "{%0,%1,%2,%3}, {%4,%5,%6,%7}, {%8,%9}, {%0,%1,%2,%3};"
        : "+f"(d[0]), "+f"(d[1]), "+f"(d[2]), "+f"(d[3])
        : "r"(a[0]), "r"(a[1]), "r"(a[2]), "r"(a[3]), "r"(b[0]), "r"(b[1]));
}
__device__ __forceinline__ uint32_t packh2(float lo, float hi) {
    __half2 h = __floats2half2_rn(lo, hi);
    return *(uint32_t*)&h;
}

// ---------------- fused conversion kernel (device globals only in device code)
__global__ __launch_bounds__(256) void conv_all(const float* __restrict__ x,
                                                const float* __restrict__ y,
                                                const float* __restrict__ w_qkv,
                                                const float* __restrict__ w_proj) {
    int blk = blockIdx.x;
    const float* src;
    __half* dst;
    size_t i;
    if (blk < 8192) {
        i = ((size_t)blk * 256 + threadIdx.x) * 4;
        src = (i < (size_t)BR * CD) ? x + i : y + (i - (size_t)BR * CD);
        dst = g_Ah + i;
    } else if (blk < 8192 + 3072) {
        i = ((size_t)(blk - 8192) * 256 + threadIdx.x) * 4;
        src = w_qkv + i;
        dst = g_Wqh + i;
    } else {
        i = ((size_t)(blk - 8192 - 3072) * 256 + threadIdx.x) * 4;
        src = w_proj + i;
        dst = g_Wph + i;
    }
    float4 v = *(const float4*)src;
    uint2 o;
    o.x = packh2(v.x, v.y); o.y = packh2(v.z, v.w);
    *(uint2*)dst = o;
}

// ---------------------------------------------------------------------------
// fp16 GEMM (R14 config — measured best): mma.m16n8k16 + ldmatrix, BK=64,
// 2-stage double-buffered cp.async.  128 thr (4 warps, 64x64 warp tiles).
// smem bytes: A stage s @ s*18432 (128x72 halves), B stage s @ 36864+s*17408
// (64x136 halves). total 71680 B.
// ---------------------------------------------------------------------------
#define GEMM_SMEM_BYTES 71680
template<int SEL>
__global__ __launch_bounds__(128) void gemm_fp16(const float* __restrict__ x,
                                                 const float* __restrict__ y,
                                                 const float* __restrict__ bias,
                                                 float* __restrict__ out) {
    extern __shared__ __half sh[];
    const int N = SEL ? CD : NQ;
    const __half* __restrict__ A = SEL ? g_Oh : g_Ah;
    const __half* __restrict__ W = SEL ? g_Wph : g_Wqh;
    const int tid = threadIdx.x, wid = tid >> 5, lane = tid & 31;
    const int bm = blockIdx.y * 128, bn = blockIdx.x * 128;
    const int wr = (wid & 1) * 64, wc = (wid >> 1) * 64;
    const uint32_t sb = smem_u32(sh);

    float acc[4][8][4];
    #pragma unroll
    for (int m = 0; m < 4; m++)
        #pragma unroll
        for (int n = 0; n < 8; n++)
            #pragma unroll
            for (int r = 0; r < 4; r++) acc[m][n][r] = 0.f;

    auto issue = [&](int c) {
        int k0 = c * 64;
        uint32_t ab = (uint32_t)(c & 1) * 18432u;
        uint32_t bb = 36864u + (uint32_t)(c & 1) * 17408u;
        #pragma unroll
        for (int j = 0; j < 8; j++) {          // A: 1024 16B units
            int u = tid + j * 128;
            int row = u >> 3, c8 = (u & 7) * 8;
            CPA16(sb + ab + (uint32_t)(row * 72 + c8) * 2u,
                  A + (size_t)(bm + row) * CD + k0 + c8);
        }
        #pragma unroll
        for (int j = 0; j < 8; j++) {          // B: 1024 16B units
            int u = tid + j * 128;
            int row = u >> 4, c8 = (u & 15) * 8;
            CPA16(sb + bb + (uint32_t)(row * 136 + c8) * 2u,
                  W + (size_t)(k0 + row) * N + bn + c8);
        }
        CP_COMMIT();
    };

    issue(0);
    for (int c = 0; c < 16; c++) {
        if (c < 15) { issue(c + 1); CP_WAIT(1); }
        else        {               CP_WAIT(0); }
        __syncthreads();
        const uint32_t abase = sb + (uint32_t)(c & 1) * 18432u;
        const uint32_t bbase = sb + 36864u + (uint32_t)(c & 1) * 17408u;
        #pragma unroll
        for (int k16 = 0; k16 < 4; k16++) {
            uint32_t a[4][4];
            #pragma unroll
            for (int m = 0; m < 4; m++) {
                uint32_t addr = abase + (uint32_t)(
                    (wr + m * 16 + (lane & 15)) * 72
                    + k16 * 16 + (lane >> 4) * 8) * 2u;
                LDSM4(a[m][0], a[m][1], a[m][2], a[m][3], addr);
            }
            #pragma unroll
            for (int nt = 0; nt < 4; nt++) {
                uint32_t b[4];
                uint32_t addr = bbase + (uint32_t)(
                    (k16 * 16 + (lane & 7) + ((lane >> 3) & 1) * 8) * 136
                    + wc + nt * 16 + (lane >> 4) * 8) * 2u;
                LDSM4T(b[0], b[1], b[2], b[3], addr);
                #pragma unroll
                for (int m = 0; m < 4; m++) {
                    mma16816(acc[m][nt * 2],     a[m], &b[0]);
                    mma16816(acc[m][nt * 2 + 1], a[m], &b[2]);
                }
            }
        }
        __syncthreads();
    }

    // epilogue: direct fragment stores
    const int er = lane >> 2, ec = (lane & 3) * 2;
    #pragma unroll
    for (int m = 0; m < 4; m++) {
        int grow0 = bm + wr + m * 16 + er;
        #pragma unroll
        for (int n = 0; n < 8; n++) {
            int gcol = bn + wc + n * 8 + ec;
            if (SEL == 0) {
                *(uint32_t*)(g_QKVh + (size_t)grow0 * NQ + gcol) =
                    packh2(acc[m][n][0], acc[m][n][1]);
                *(uint32_t*)(g_QKVh + (size_t)(grow0 + 8) * NQ + gcol) =
                    packh2(acc[m][n][2], acc[m][n][3]);
            } else {
                #pragma unroll
                for (int hrow = 0; hrow < 2; hrow++) {
                    int grow = grow0 + hrow * 8;
                    const float* res = ((grow < BR) ? x + (size_t)grow * CD
                                                    : y + (size_t)(grow - BR) * CD) + gcol;
                    float2 rv = *(const float2*)res;
                    float2 bv = *(const float2*)(bias + gcol);
                    float2 o;
                    o.x = acc[m][n][hrow * 2]     + bv.x + rv.x;
                    o.y = acc[m][n][hrow * 2 + 1] + bv.y + rv.y;
                    *(float2*)(out + (size_t)grow * CD + gcol) = o;
                }
            }
        }
    }
}

// ---------------------------------------------------------------------------
// Flash attention — exact R12 configuration (measured best: 412 µs total).
// fp16 mma + ldmatrix + register softmax; 2-stage KV; 256 thr (8 warps,
// 16 q-rows each), q-tile 128, no occupancy pragma.
// smem: Qs h[128][72] @0, KV buf b @ 18432+b*18432 (K then V h[64][72]).
// ---------------------------------------------------------------------------
#define ATT_SMEM_BYTES 55296
__global__ __launch_bounds__(256) void attn_fa() {
    extern __shared__ __align__(16) char shc[];
    const uint32_t sb = smem_u32(shc);
    const int tid = threadIdx.x, wid = tid >> 5, lane = tid & 31;

    const int job = blockIdx.y;
    const int p = job >> 5, b = (job >> 4) & 1, h = job & 15;
    const int q0 = blockIdx.x * 128;
    const size_t base  = (size_t)(p * 2 + b) * SEQ * NQ;
    const size_t baseV = (size_t)((1 - p) * 2 + b) * SEQ * NQ;
    const __half* qp = g_QKVh + base + (size_t)h * 64;
    const __half* kp = g_QKVh + base + CD + (size_t)h * 64;
    const __half* vp = g_QKVh + baseV + 2 * CD + (size_t)h * 64;

    auto issueKV = [&](int kt) {
        uint32_t off = 18432u + (uint32_t)(kt & 1) * 18432u;
        #pragma unroll
        for (int j = 0; j < 2; j++) {
            int u = tid + j * 256;
            int r = u >> 3, c8 = (u & 7) * 8;
            size_t go = (size_t)(kt * 64 + r) * NQ + c8;
            uint32_t so = (uint32_t)(r * 72 + c8) * 2u;
            CPA16(sb + off + so, kp + go);
            CPA16(sb + off + 9216u + so, vp + go);
        }
        CP_COMMIT();
    };

    #pragma unroll
    for (int j = 0; j < 4; j++) {
        int u = tid + j * 256;
        int r = u >> 3, c8 = (u & 7) * 8;
        CPA16(sb + (uint32_t)(r * 72 + c8) * 2u, qp + (size_t)(q0 + r) * NQ + c8);
    }
    issueKV(0);
    CP_WAIT(0);
    __syncthreads();

    uint32_t qa[4][4];
    #pragma unroll
    for (int c = 0; c < 4; c++) {
        uint32_t addr = sb + (uint32_t)((wid * 16 + (lane & 15)) * 72
                                        + c * 16 + (lane >> 4) * 8) * 2u;
        LDSM4(qa[c][0], qa[c][1], qa[c][2], qa[c][3], addr);
    }

    float o[8][4];
    #pragma unroll
    for (int n = 0; n < 8; n++)
        #pragma unroll
        for (int r = 0; r < 4; r++) o[n][r] = 0.f;
    float l0 = 0.f, l1 = 0.f;
    const float SC = 0.18033688f;           // D^-0.5 * log2(e)

    for (int kt = 0; kt < 32; kt++) {
        if (kt < 31) { issueKV(kt + 1); CP_WAIT(1); }
        else         {                  CP_WAIT(0); }
        __syncthreads();
        const uint32_t kbase = sb + 18432u + (uint32_t)(kt & 1) * 18432u;
        const uint32_t vbase = kbase + 9216u;

        float s[8][4];
        #pragma unroll
        for (int n = 0; n < 8; n++)
            #pragma unroll
            for (int r = 0; r < 4; r++) s[n][r] = 0.f;

        #pragma unroll
        for (int c = 0; c < 4; c++) {
            uint32_t kb[4][4];
            #pragma unroll
            for (int t = 0; t < 4; t++) {
                uint32_t addr = kbase + (uint32_t)(
                    (t * 16 + (lane & 7) + (lane >> 4) * 8) * 72
                    + c * 16 + ((lane >> 3) & 1) * 8) * 2u;
                LDSM4(kb[t][0], kb[t][1], kb[t][2], kb[t][3], addr);
            }
            #pragma unroll
            for (int t = 0; t < 4; t++) {
                mma16816(s[t * 2],     qa[c], &kb[t][0]);
                mma16816(s[t * 2 + 1], qa[c], &kb[t][2]);
            }
        }

        float rs0 = 0.f, rs1 = 0.f;
        #pragma unroll
        for (int n = 0; n < 8; n++) {
            float e0 = ex2(s[n][0] * SC), e1 = ex2(s[n][1] * SC);
            float e2 = ex2(s[n][2] * SC), e3 = ex2(s[n][3] * SC);
            s[n][0] = e0; s[n][1] = e1; s[n][2] = e2; s[n][3] = e3;
            rs0 += e0 + e1; rs1 += e2 + e3;
        }
        rs0 += __shfl_xor_sync(0xffffffffu, rs0, 1);
        rs0 += __shfl_xor_sync(0xffffffffu, rs0, 2);
        rs1 += __shfl_xor_sync(0xffffffffu, rs1, 1);
        rs1 += __shfl_xor_sync(0xffffffffu, rs1, 2);
        l0 += rs0; l1 += rs1;

        uint32_t pa[4][4];
        #pragma unroll
        for (int c2 = 0; c2 < 4; c2++) {
            pa[c2][0] = packh2(s[c2 * 2][0],     s[c2 * 2][1]);
            pa[c2][1] = packh2(s[c2 * 2][2],     s[c2 * 2][3]);
            pa[c2][2] = packh2(s[c2 * 2 + 1][0], s[c2 * 2 + 1][1]);
            pa[c2][3] = packh2(s[c2 * 2 + 1][2], s[c2 * 2 + 1][3]);
        }

        #pragma unroll
        for (int c2 = 0; c2 < 4; c2++) {
            #pragma unroll
            for (int j = 0; j < 4; j++) {
                uint32_t vb[4];
                uint32_t addr = vbase + (uint32_t)(
                    (c2 * 16 + (lane & 7) + ((lane >> 3) & 1) * 8) * 72
                    + j * 16 + (lane >> 4) * 8) * 2u;
                LDSM4T(vb[0], vb[1], vb[2], vb[3], addr);
                mma16816(o[j * 2],     pa[c2], &vb[0]);
                mma16816(o[j * 2 + 1], pa[c2], &vb[2]);
            }
        }
        __syncthreads();
    }

    // epilogue: normalize, write fp16 g_Oh
    const float inv0 = 1.f / l0, inv1 = 1.f / l1;
    const size_t rbase = (size_t)(p * 2 + b) * SEQ + q0 + wid * 16;
    const size_t r0 = rbase + (lane >> 2), r1 = r0 + 8;
    const int colb = h * 64 + (lane & 3) * 2;
    #pragma unroll
    for (int n = 0; n < 8; n++) {
        *(uint32_t*)(g_Oh + r0 * CD + colb + n * 8) =
            packh2(o[n][0] * inv0, o[n][1] * inv0);
        *(uint32_t*)(g_Oh + r1 * CD + colb + n * 8) =
            packh2(o[n][2] * inv1, o[n][3] * inv1);
    }
}

// ---------------------------------------------------------------------------
extern "C" void kernel_launch(void* const* d_in, const int* in_sizes, int n_in,
                              void* d_out, int out_size) {
    const float* x      = (const float*)d_in[0];
    const float* y      = (const float*)d_in[1];
    const float* w_qkv  = (const float*)d_in[2];
    const float* w_proj = (const float*)d_in[3];
    const float* b_proj = (const float*)d_in[4];
    float* out = (float*)d_out;

    cudaFuncSetAttribute(gemm_fp16<0>, cudaFuncAttributeMaxDynamicSharedMemorySize, GEMM_SMEM_BYTES);
    cudaFuncSetAttribute(gemm_fp16<1>, cudaFuncAttributeMaxDynamicSharedMemorySize, GEMM_SMEM_BYTES);
    cudaFuncSetAttribute(attn_fa,      cudaFuncAttributeMaxDynamicSharedMemorySize, ATT_SMEM_BYTES);

    conv_all<<<8192 + 3072 + 1024, 256>>>(x, y, w_qkv, w_proj);

    gemm_fp16<0><<<dim3(NQ / 128, RWS / 128), 128, GEMM_SMEM_BYTES>>>(x, y, nullptr, nullptr);
    attn_fa<<<dim3(SEQ / 128, 64), 256, ATT_SMEM_BYTES>>>();
    gemm_fp16<1><<<dim3(CD / 128, RWS / 128), 128, GEMM_SMEM_BYTES>>>(x, y, b_proj, out);
}

// round 17
// speedup vs baseline: 1.0911x; 1.0556x over previous
#include <cuda_runtime.h>
#include <cuda_fp16.h>
#include <cstdint>

#define SEQ 2048
#define CD  1024
#define NQ  3072
#define RWS 8192
#define BR  4096

// scratch (device globals; allocation forbidden)
__device__ __half g_Ah [(size_t)RWS * CD];   // fp16 concat(x,y)
__device__ __half g_Wqh[(size_t)CD * NQ];    // fp16 w_qkv [K,N]
__device__ __half g_Wph[(size_t)CD * CD];    // fp16 w_proj [K,N]
__device__ __half g_QKVh[(size_t)RWS * NQ];  // fp16 qkv [row, 3C]
__device__ __half g_Oh [(size_t)RWS * CD];   // fp16 attention out

__device__ __forceinline__ uint32_t smem_u32(const void* p) {
    uint32_t a;
    asm("{ .reg .u64 t; cvta.to.shared.u64 t, %1; cvt.u32.u64 %0, t; }" : "=r"(a) : "l"(p));
    return a;
}
__device__ __forceinline__ float ex2(float x) {
    float r; asm("ex2.approx.f32 %0, %1;" : "=f"(r) : "f"(x)); return r;
}
#define CPA16(dst, src) \
    asm volatile("cp.async.cg.shared.global [%0], [%1], 16;" :: "r"(dst), "l"(src) : "memory")
#define CP_COMMIT() asm volatile("cp.async.commit_group;" ::: "memory")
#define CP_WAIT(n)  asm volatile("cp.async.wait_group %0;" :: "n"(n) : "memory")

#define LDSM4(r0, r1, r2, r3, addr)                                         \
    asm volatile("ldmatrix.sync.aligned.m8n8.x4.shared.b16 {%0,%1,%2,%3}, [%4];" \
        : "=r"(r0), "=r"(r1), "=r"(r2), "=r"(r3) : "r"(addr))
#define LDSM4T(r0, r1, r2, r3, addr)                                        \
    asm volatile("ldmatrix.sync.aligned.m8n8.x4.trans.shared.b16 {%0,%1,%2,%3}, [%4];" \
        : "=r"(r0), "=r"(r1), "=r"(r2), "=r"(r3) : "r"(addr))

__device__ __forceinline__ void mma16816(float* d, const uint32_t* a,
                                         const uint32_t* b) {
    asm volatile(
        "mma.sync.aligned.m16n8k16.row.col.f32.f16.f16.f32 "
        "{%0,%1,%2,%3}, {%4,%5,%6,%7}, {%8,%9}, {%0,%1,%2,%3};"
        : "+f"(d[0]), "+f"(d[1]), "+f"(d[2]), "+f"(d[3])
        : "r"(a[0]), "r"(a[1]), "r"(a[2]), "r"(a[3]), "r"(b[0]), "r"(b[1]));
}
__device__ __forceinline__ uint32_t packh2(float lo, float hi) {
    __half2 h = __floats2half2_rn(lo, hi);
    return *(uint32_t*)&h;
}

// ---------------- fused conversion kernel ----------------
__global__ __launch_bounds__(256) void conv_all(const float* __restrict__ x,
                                                const float* __restrict__ y,
                                                const float* __restrict__ w_qkv,
                                                const float* __restrict__ w_proj) {
    int blk = blockIdx.x;
    const float* src;
    __half* dst;
    size_t i;
    if (blk < 8192) {
        i = ((size_t)blk * 256 + threadIdx.x) * 4;
        src = (i < (size_t)BR * CD) ? x + i : y + (i - (size_t)BR * CD);
        dst = g_Ah + i;
    } else if (blk < 8192 + 3072) {
        i = ((size_t)(blk - 8192) * 256 + threadIdx.x) * 4;
        src = w_qkv + i;
        dst = g_Wqh + i;
    } else {
        i = ((size_t)(blk - 8192 - 3072) * 256 + threadIdx.x) * 4;
        src = w_proj + i;
        dst = g_Wph + i;
    }
    float4 v = *(const float4*)src;
    uint2 o;
    o.x = packh2(v.x, v.y); o.y = packh2(v.z, v.w);
    *(uint2*)dst = o;
}

// ---------------------------------------------------------------------------
// fp16 GEMM, template BK: <0,32> = qkv (measured-best), <1,64> = proj (best).
// 128 thr (4 warps, 64x64 warp tiles), 2-stage cp.async.
// smem: A stage s @ s*ASTAGE (128 x (BK+8) halves),
//       B stage s @ 2*ASTAGE + s*BSTAGE (BK x 136 halves).
// ---------------------------------------------------------------------------
template<int SEL, int BK>
__global__ __launch_bounds__(128) void gemm_fp16(const float* __restrict__ x,
                                                 const float* __restrict__ y,
                                                 const float* __restrict__ bias,
                                                 float* __restrict__ out) {
    constexpr int ASTAGE = 128 * (BK + 8) * 2;   // bytes
    constexpr int BSTAGE = BK * 136 * 2;         // bytes
    constexpr int KITERS = CD / BK;
    constexpr int UNITS  = BK / 8;               // 16B units per A row

    extern __shared__ __half sh[];
    const int N = SEL ? CD : NQ;
    const __half* __restrict__ A = SEL ? g_Oh : g_Ah;
    const __half* __restrict__ W = SEL ? g_Wph : g_Wqh;
    const int tid = threadIdx.x, wid = tid >> 5, lane = tid & 31;
    const int bm = blockIdx.y * 128, bn = blockIdx.x * 128;
    const int wr = (wid & 1) * 64, wc = (wid >> 1) * 64;
    const uint32_t sb = smem_u32(sh);

    float acc[4][8][4];
    #pragma unroll
    for (int m = 0; m < 4; m++)
        #pragma unroll
        for (int n = 0; n < 8; n++)
            #pragma unroll
            for (int r = 0; r < 4; r++) acc[m][n][r] = 0.f;

    auto issue = [&](int c) {
        int k0 = c * BK;
        uint32_t ab = (uint32_t)(c & 1) * ASTAGE;
        uint32_t bb = 2u * ASTAGE + (uint32_t)(c & 1) * BSTAGE;
        #pragma unroll
        for (int j = 0; j < UNITS; j++) {      // A: 128*BK/8 16B units
            int u = tid + j * 128;
            int row = u / UNITS, c8 = (u % UNITS) * 8;
            CPA16(sb + ab + (uint32_t)(row * (BK + 8) + c8) * 2u,
                  A + (size_t)(bm + row) * CD + k0 + c8);
        }
        #pragma unroll
        for (int j = 0; j < UNITS; j++) {      // B: BK*16 16B units
            int u = tid + j * 128;
            int row = u >> 4, c8 = (u & 15) * 8;
            CPA16(sb + bb + (uint32_t)(row * 136 + c8) * 2u,
                  W + (size_t)(k0 + row) * N + bn + c8);
        }
        CP_COMMIT();
    };

    issue(0);
    for (int c = 0; c < KITERS; c++) {
        if (c < KITERS - 1) { issue(c + 1); CP_WAIT(1); }
        else                {               CP_WAIT(0); }
        __syncthreads();
        const uint32_t abase = sb + (uint32_t)(c & 1) * ASTAGE;
        const uint32_t bbase = sb + 2u * ASTAGE + (uint32_t)(c & 1) * BSTAGE;
        #pragma unroll
        for (int k16 = 0; k16 < BK / 16; k16++) {
            uint32_t a[4][4];
            #pragma unroll
            for (int m = 0; m < 4; m++) {
                uint32_t addr = abase + (uint32_t)(
                    (wr + m * 16 + (lane & 15)) * (BK + 8)
                    + k16 * 16 + (lane >> 4) * 8) * 2u;
                LDSM4(a[m][0], a[m][1], a[m][2], a[m][3], addr);
            }
            #pragma unroll
            for (int nt = 0; nt < 4; nt++) {
                uint32_t b[4];
                uint32_t addr = bbase + (uint32_t)(
                    (k16 * 16 + (lane & 7) + ((lane >> 3) & 1) * 8) * 136
                    + wc + nt * 16 + (lane >> 4) * 8) * 2u;
                LDSM4T(b[0], b[1], b[2], b[3], addr);
                #pragma unroll
                for (int m = 0; m < 4; m++) {
                    mma16816(acc[m][nt * 2],     a[m], &b[0]);
                    mma16816(acc[m][nt * 2 + 1], a[m], &b[2]);
                }
            }
        }
        __syncthreads();
    }

    // epilogue: direct fragment stores
    const int er = lane >> 2, ec = (lane & 3) * 2;
    #pragma unroll
    for (int m = 0; m < 4; m++) {
        int grow0 = bm + wr + m * 16 + er;
        #pragma unroll
        for (int n = 0; n < 8; n++) {
            int gcol = bn + wc + n * 8 + ec;
            if (SEL == 0) {
                *(uint32_t*)(g_QKVh + (size_t)grow0 * NQ + gcol) =
                    packh2(acc[m][n][0], acc[m][n][1]);
                *(uint32_t*)(g_QKVh + (size_t)(grow0 + 8) * NQ + gcol) =
                    packh2(acc[m][n][2], acc[m][n][3]);
            } else {
                #pragma unroll
                for (int hrow = 0; hrow < 2; hrow++) {
                    int grow = grow0 + hrow * 8;
                    const float* res = ((grow < BR) ? x + (size_t)grow * CD
                                                    : y + (size_t)(grow - BR) * CD) + gcol;
                    float2 rv = *(const float2*)res;
                    float2 bv = *(const float2*)(bias + gcol);
                    float2 o;
                    o.x = acc[m][n][hrow * 2]     + bv.x + rv.x;
                    o.y = acc[m][n][hrow * 2 + 1] + bv.y + rv.y;
                    *(float2*)(out + (size_t)grow * CD + gcol) = o;
                }
            }
        }
    }
}
#define GEMM_SMEM_QKV  37888   // BK=32
#define GEMM_SMEM_PROJ 71680   // BK=64

// ---------------------------------------------------------------------------
// Flash attention — R12 structure + __launch_bounds__(256,2) (measured ~8us
// faster via R14 vs R16 isolation). fp16 mma + ldmatrix + register softmax,
// 2-stage KV, 256 thr (8 warps, 16 q-rows each), q-tile 128.
// smem: Qs h[128][72] @0, KV buf b @ 18432+b*18432 (K then V h[64][72]).
// ---------------------------------------------------------------------------
#define ATT_SMEM_BYTES 55296
__global__ __launch_bounds__(256, 2) void attn_fa() {
    extern __shared__ __align__(16) char shc[];
    const uint32_t sb = smem_u32(shc);
    const int tid = threadIdx.x, wid = tid >> 5, lane = tid & 31;

    const int job = blockIdx.y;
    const int p = job >> 5, b = (job >> 4) & 1, h = job & 15;
    const int q0 = blockIdx.x * 128;
    const size_t base  = (size_t)(p * 2 + b) * SEQ * NQ;
    const size_t baseV = (size_t)((1 - p) * 2 + b) * SEQ * NQ;
    const __half* qp = g_QKVh + base + (size_t)h * 64;
    const __half* kp = g_QKVh + base + CD + (size_t)h * 64;
    const __half* vp = g_QKVh + baseV + 2 * CD + (size_t)h * 64;

    auto issueKV = [&](int kt) {
        uint32_t off = 18432u + (uint32_t)(kt & 1) * 18432u;
        #pragma unroll
        for (int j = 0; j < 2; j++) {
            int u = tid + j * 256;
            int r = u >> 3, c8 = (u & 7) * 8;
            size_t go = (size_t)(kt * 64 + r) * NQ + c8;
            uint32_t so = (uint32_t)(r * 72 + c8) * 2u;
            CPA16(sb + off + so, kp + go);
            CPA16(sb + off + 9216u + so, vp + go);
        }
        CP_COMMIT();
    };

    #pragma unroll
    for (int j = 0; j < 4; j++) {
        int u = tid + j * 256;
        int r = u >> 3, c8 = (u & 7) * 8;
        CPA16(sb + (uint32_t)(r * 72 + c8) * 2u, qp + (size_t)(q0 + r) * NQ + c8);
    }
    issueKV(0);
    CP_WAIT(0);
    __syncthreads();

    uint32_t qa[4][4];
    #pragma unroll
    for (int c = 0; c < 4; c++) {
        uint32_t addr = sb + (uint32_t)((wid * 16 + (lane & 15)) * 72
                                        + c * 16 + (lane >> 4) * 8) * 2u;
        LDSM4(qa[c][0], qa[c][1], qa[c][2], qa[c][3], addr);
    }

    float o[8][4];
    #pragma unroll
    for (int n = 0; n < 8; n++)
        #pragma unroll
        for (int r = 0; r < 4; r++) o[n][r] = 0.f;
    float l0 = 0.f, l1 = 0.f;
    const float SC = 0.18033688f;           // D^-0.5 * log2(e)

    for (int kt = 0; kt < 32; kt++) {
        if (kt < 31) { issueKV(kt + 1); CP_WAIT(1); }
        else         {                  CP_WAIT(0); }
        __syncthreads();
        const uint32_t kbase = sb + 18432u + (uint32_t)(kt & 1) * 18432u;
        const uint32_t vbase = kbase + 9216u;

        float s[8][4];
        #pragma unroll
        for (int n = 0; n < 8; n++)
            #pragma unroll
            for (int r = 0; r < 4; r++) s[n][r] = 0.f;

        #pragma unroll
        for (int c = 0; c < 4; c++) {
            uint32_t kb[4][4];
            #pragma unroll
            for (int t = 0; t < 4; t++) {
                uint32_t addr = kbase + (uint32_t)(
                    (t * 16 + (lane & 7) + (lane >> 4) * 8) * 72
                    + c * 16 + ((lane >> 3) & 1) * 8) * 2u;
                LDSM4(kb[t][0], kb[t][1], kb[t][2], kb[t][3], addr);
            }
            #pragma unroll
            for (int t = 0; t < 4; t++) {
                mma16816(s[t * 2],     qa[c], &kb[t][0]);
                mma16816(s[t * 2 + 1], qa[c], &kb[t][2]);
            }
        }

        float rs0 = 0.f, rs1 = 0.f;
        #pragma unroll
        for (int n = 0; n < 8; n++) {
            float e0 = ex2(s[n][0] * SC), e1 = ex2(s[n][1] * SC);
            float e2 = ex2(s[n][2] * SC), e3 = ex2(s[n][3] * SC);
            s[n][0] = e0; s[n][1] = e1; s[n][2] = e2; s[n][3] = e3;
            rs0 += e0 + e1; rs1 += e2 + e3;
        }
        rs0 += __shfl_xor_sync(0xffffffffu, rs0, 1);
        rs0 += __shfl_xor_sync(0xffffffffu, rs0, 2);
        rs1 += __shfl_xor_sync(0xffffffffu, rs1, 1);
        rs1 += __shfl_xor_sync(0xffffffffu, rs1, 2);
        l0 += rs0; l1 += rs1;

        uint32_t pa[4][4];
        #pragma unroll
        for (int c2 = 0; c2 < 4; c2++) {
            pa[c2][0] = packh2(s[c2 * 2][0],     s[c2 * 2][1]);
            pa[c2][1] = packh2(s[c2 * 2][2],     s[c2 * 2][3]);
            pa[c2][2] = packh2(s[c2 * 2 + 1][0], s[c2 * 2 + 1][1]);
            pa[c2][3] = packh2(s[c2 * 2 + 1][2], s[c2 * 2 + 1][3]);
        }

        #pragma unroll
        for (int c2 = 0; c2 < 4; c2++) {
            #pragma unroll
            for (int j = 0; j < 4; j++) {
                uint32_t vb[4];
                uint32_t addr = vbase + (uint32_t)(
                    (c2 * 16 + (lane & 7) + ((lane >> 3) & 1) * 8) * 72
                    + j * 16 + (lane >> 4) * 8) * 2u;
                LDSM4T(vb[0], vb[1], vb[2], vb[3], addr);
                mma16816(o[j * 2],     pa[c2], &vb[0]);
                mma16816(o[j * 2 + 1], pa[c2], &vb[2]);
            }
        }
        __syncthreads();
    }

    // epilogue: normalize, write fp16 g_Oh
    const float inv0 = 1.f / l0, inv1 = 1.f / l1;
    const size_t rbase = (size_t)(p * 2 + b) * SEQ + q0 + wid * 16;
    const size_t r0 = rbase + (lane >> 2), r1 = r0 + 8;
    const int colb = h * 64 + (lane & 3) * 2;
    #pragma unroll
    for (int n = 0; n < 8; n++) {
        *(uint32_t*)(g_Oh + r0 * CD + colb + n * 8) =
            packh2(o[n][0] * inv0, o[n][1] * inv0);
        *(uint32_t*)(g_Oh + r1 * CD + colb + n * 8) =
            packh2(o[n][2] * inv1, o[n][3] * inv1);
    }
}

// ---------------------------------------------------------------------------
extern "C" void kernel_launch(void* const* d_in, const int* in_sizes, int n_in,
                              void* d_out, int out_size) {
    const float* x      = (const float*)d_in[0];
    const float* y      = (const float*)d_in[1];
    const float* w_qkv  = (const float*)d_in[2];
    const float* w_proj = (const float*)d_in[3];
    const float* b_proj = (const float*)d_in[4];
    float* out = (float*)d_out;

    cudaFuncSetAttribute((const void*)gemm_fp16<0, 32>,
                         cudaFuncAttributeMaxDynamicSharedMemorySize, GEMM_SMEM_QKV);
    cudaFuncSetAttribute((const void*)gemm_fp16<1, 64>,
                         cudaFuncAttributeMaxDynamicSharedMemorySize, GEMM_SMEM_PROJ);
    cudaFuncSetAttribute((const void*)attn_fa,
                         cudaFuncAttributeMaxDynamicSharedMemorySize, ATT_SMEM_BYTES);

    conv_all<<<8192 + 3072 + 1024, 256>>>(x, y, w_qkv, w_proj);

    gemm_fp16<0, 32><<<dim3(NQ / 128, RWS / 128), 128, GEMM_SMEM_QKV>>>(x, y, nullptr, nullptr);
    attn_fa<<<dim3(SEQ / 128, 64), 256, ATT_SMEM_BYTES>>>();
    gemm_fp16<1, 64><<<dim3(CD / 128, RWS / 128), 128, GEMM_SMEM_PROJ>>>(x, y, b_proj, out);
}